// round 13
// baseline (speedup 1.0000x reference)
#include <cuda_runtime.h>
#include <cuda_fp16.h>
#include <cstdint>
#include <math.h>

// ---------------- scratch (no allocations allowed) ----------------
#define N_LEAVES_MAX 100000
#define MAXB 256
#define GRID_B 148
#define NSIMS 148

__device__ __align__(16) __half g_dleaf[N_LEAVES_MAX + 128];
__device__ int    g_maxint;          // max d as ordered int (positive floats)
__device__ float4 g_part[MAXB];      // (sum_exp, sum_sims_exp, -, -)
__device__ float  g_su[NSIMS];       // sims partial sums
__device__ int    g_chk[NSIMS];      // keeps index warm-loads alive

// ---------------- mbarrier / bulk-copy helpers (kernel B staging) ----------------
__device__ __forceinline__ void mbar_init(unsigned int mbar, unsigned int cnt) {
    asm volatile("mbarrier.init.shared.b64 [%0], %1;" :: "r"(mbar), "r"(cnt) : "memory");
}
__device__ __forceinline__ void mbar_expect_tx(unsigned int mbar, unsigned int bytes) {
    asm volatile("mbarrier.arrive.expect_tx.shared.b64 _, [%0], %1;"
                 :: "r"(mbar), "r"(bytes) : "memory");
}
__device__ __forceinline__ void mbar_wait(unsigned int mbar, unsigned int phase) {
    asm volatile(
        "{\n\t"
        ".reg .pred P1;\n\t"
        "WAIT_LOOP_%=:\n\t"
        "mbarrier.try_wait.parity.acquire.cta.shared::cta.b64 P1, [%0], %1, 0x989680;\n\t"
        "@P1 bra.uni WAIT_DONE_%=;\n\t"
        "bra.uni WAIT_LOOP_%=;\n\t"
        "WAIT_DONE_%=:\n\t"
        "}"
        :: "r"(mbar), "r"(phase) : "memory");
}
__device__ __forceinline__ void bulk_g2s(unsigned int dst, const void* src,
                                         unsigned int bytes, unsigned int mbar) {
    asm volatile(
        "cp.async.bulk.shared::cluster.global.mbarrier::complete_tx::bytes [%0], [%1], %2, [%3];"
        :: "r"(dst), "l"(src), "r"(bytes), "r"(mbar) : "memory");
}

// ---------------- Kernel A: heterogeneous grid ----------------
// blocks [0, NSIMS): stream pairs (sum sims, warm l_idx/r_idx into L2)
// blocks [NSIMS, ..): leaf distances (R10 layout: 8 leaves / warp-iter)
__global__ __launch_bounds__(256, 4) void leaf_dist_kernel(
        const int* __restrict__ lca,
        const float* __restrict__ emb,
        const float* __restrict__ leaves,
        const float* __restrict__ scale,
        const int* __restrict__ l_idx,
        const int* __restrict__ r_idx,
        const float* __restrict__ sims,
        int n_leaves, int n_pairs)
{
    __shared__ __align__(16) float s_e[128];
    __shared__ float s_red[256];
    __shared__ int   s_chk[256];
    __shared__ float s_nx, s_inv;

    const int t = threadIdx.x;

    // ================= sims-stream blocks =================
    if (blockIdx.x < NSIMS) {
        const int sb = blockIdx.x;
        float su = 0.0f;
        int   chk = 0;

        const int n4 = n_pairs >> 2;
        const int4*   l4 = reinterpret_cast<const int4*>(l_idx);
        const int4*   r4 = reinterpret_cast<const int4*>(r_idx);
        const float4* s4 = reinterpret_cast<const float4*>(sims);
        const int stride = NSIMS * 256;

        for (int i = sb * 256 + t; i < n4; i += stride) {
            int4   a = l4[i];
            int4   b = r4[i];
            float4 s = s4[i];
            su  += (s.x + s.y) + (s.z + s.w);
            chk += (a.x + a.y + a.z + a.w) + (b.x + b.y + b.z + b.w);
        }
        if (sb == 0) {
            for (int i = n4 * 4 + t; i < n_pairs; i += 256) {
                su  += sims[i];
                chk += l_idx[i] + r_idx[i];
            }
        }
        s_red[t] = su; s_chk[t] = chk;
        __syncthreads();
        for (int off = 128; off > 0; off >>= 1) {
            if (t < off) { s_red[t] += s_red[t + off]; s_chk[t] += s_chk[t + off]; }
            __syncthreads();
        }
        if (t == 0) { g_su[sb] = s_red[0]; g_chk[sb] = s_chk[0]; }
        return;
    }

    // ================= leaf-distance blocks =================
    // ---- build e1 = emb[lca]/max(||.||,1e-12) * clip(scale) ----
    const float* erow = emb + (long long)lca[0] * 128;
    float w = 0.0f;
    if (t < 128) { w = erow[t]; s_red[t] = w * w; }
    __syncthreads();
    for (int off = 64; off > 0; off >>= 1) {
        if (t < off) s_red[t] += s_red[t + off];
        __syncthreads();
    }
    if (t == 0) {
        float norm2  = s_red[0];
        float s      = fminf(fmaxf(scale[0], 0.01f), 1.0f - 0.001f);
        float factor = s / fmaxf(sqrtf(norm2), 1e-12f);
        float nx     = factor * factor * norm2;
        s_nx  = nx;
        s_inv = 1.0f / (1.0f - nx);
        s_red[0] = factor;
    }
    __syncthreads();
    if (t < 128) s_e[t] = w * s_red[0];
    __syncthreads();

    const int lane = t & 31;
    const int sub  = lane & 7;
    const int grp  = lane >> 3;
    const float4* er = reinterpret_cast<const float4*>(s_e);
    const float4 ea = er[sub], eb = er[sub + 8], ec = er[sub + 16], ed = er[sub + 24];
    const float nx = s_nx, inv = s_inv;

    const float4* leaves4 = reinterpret_cast<const float4*>(leaves);
    const int lbx     = blockIdx.x - NSIMS;
    const int gwarp   = (lbx * 256 + t) >> 5;
    const int nwarps  = ((gridDim.x - NSIMS) * 256) >> 5;
    const int ngrp8   = (n_leaves + 7) >> 3;

    float dmax = 0.0f;

    for (int g8 = gwarp; g8 < ngrp8; g8 += nwarps) {
        const int  leafA = g8 * 8 + grp;
        const int  leafB = leafA + 4;
        const bool okA   = leafA < n_leaves;
        const bool okB   = leafB < n_leaves;
        const float4* rowA = leaves4 + (size_t)(okA ? leafA : 0) * 32;
        const float4* rowB = leaves4 + (size_t)(okB ? leafB : 0) * 32;

        float4 a0 = __ldg(rowA + sub);
        float4 a1 = __ldg(rowA + sub + 8);
        float4 a2 = __ldg(rowA + sub + 16);
        float4 a3 = __ldg(rowA + sub + 24);
        float4 b0 = __ldg(rowB + sub);
        float4 b1 = __ldg(rowB + sub + 8);
        float4 b2 = __ldg(rowB + sub + 16);
        float4 b3 = __ldg(rowB + sub + 24);

        float dotA, nyA;
        dotA = ea.x * a0.x + ea.y * a0.y + ea.z * a0.z + ea.w * a0.w;
        nyA  = a0.x * a0.x + a0.y * a0.y + a0.z * a0.z + a0.w * a0.w;
        dotA = fmaf(eb.x, a1.x, fmaf(eb.y, a1.y, fmaf(eb.z, a1.z, fmaf(eb.w, a1.w, dotA))));
        nyA  = fmaf(a1.x, a1.x, fmaf(a1.y, a1.y, fmaf(a1.z, a1.z, fmaf(a1.w, a1.w, nyA))));
        dotA = fmaf(ec.x, a2.x, fmaf(ec.y, a2.y, fmaf(ec.z, a2.z, fmaf(ec.w, a2.w, dotA))));
        nyA  = fmaf(a2.x, a2.x, fmaf(a2.y, a2.y, fmaf(a2.z, a2.z, fmaf(a2.w, a2.w, nyA))));
        dotA = fmaf(ed.x, a3.x, fmaf(ed.y, a3.y, fmaf(ed.z, a3.z, fmaf(ed.w, a3.w, dotA))));
        nyA  = fmaf(a3.x, a3.x, fmaf(a3.y, a3.y, fmaf(a3.z, a3.z, fmaf(a3.w, a3.w, nyA))));

        float dotB, nyB;
        dotB = ea.x * b0.x + ea.y * b0.y + ea.z * b0.z + ea.w * b0.w;
        nyB  = b0.x * b0.x + b0.y * b0.y + b0.z * b0.z + b0.w * b0.w;
        dotB = fmaf(eb.x, b1.x, fmaf(eb.y, b1.y, fmaf(eb.z, b1.z, fmaf(eb.w, b1.w, dotB))));
        nyB  = fmaf(b1.x, b1.x, fmaf(b1.y, b1.y, fmaf(b1.z, b1.z, fmaf(b1.w, b1.w, nyB))));
        dotB = fmaf(ec.x, b2.x, fmaf(ec.y, b2.y, fmaf(ec.z, b2.z, fmaf(ec.w, b2.w, dotB))));
        nyB  = fmaf(b2.x, b2.x, fmaf(b2.y, b2.y, fmaf(b2.z, b2.z, fmaf(b2.w, b2.w, nyB))));
        dotB = fmaf(ed.x, b3.x, fmaf(ed.y, b3.y, fmaf(ed.z, b3.z, fmaf(ed.w, b3.w, dotB))));
        nyB  = fmaf(b3.x, b3.x, fmaf(b3.y, b3.y, fmaf(b3.z, b3.z, fmaf(b3.w, b3.w, nyB))));

        #pragma unroll
        for (int o = 1; o < 8; o <<= 1) {
            dotA += __shfl_xor_sync(0xffffffffu, dotA, o);
            nyA  += __shfl_xor_sync(0xffffffffu, nyA,  o);
            dotB += __shfl_xor_sync(0xffffffffu, dotB, o);
            nyB  += __shfl_xor_sync(0xffffffffu, nyB,  o);
        }

        if (sub == 0) {
            if (okA) {
                float sq  = nx - 2.0f * dotA + nyA;
                float arg = fmaxf(1.0f + 2.0f * sq * inv / (1.0f - nyA), 1.0f + 1e-7f);
                float d = acoshf(arg);
                g_dleaf[leafA] = __float2half(d);
                dmax = fmaxf(dmax, d);
            }
            if (okB) {
                float sq  = nx - 2.0f * dotB + nyB;
                float arg = fmaxf(1.0f + 2.0f * sq * inv / (1.0f - nyB), 1.0f + 1e-7f);
                float d = acoshf(arg);
                g_dleaf[leafB] = __float2half(d);
                dmax = fmaxf(dmax, d);
            }
        }
    }

    // ---- block max -> global atomicMax (deterministic) ----
    s_red[t] = dmax;
    __syncthreads();
    for (int off = 128; off > 0; off >>= 1) {
        if (t < off) s_red[t] = fmaxf(s_red[t], s_red[t + off]);
        __syncthreads();
    }
    if (t == 0) atomicMax(&g_maxint, __float_as_int(s_red[0]));
}

// ---------------- Kernel B: branchless softmax partial sums (pairs now L2-hot) ----------------
__global__ __launch_bounds__(1024) void pair_reduce_kernel(
        const int* __restrict__ l_idx,
        const int* __restrict__ r_idx,
        const float* __restrict__ sims,
        int n_pairs, int n_leaves)
{
    extern __shared__ __half s_tab[];
    __shared__ float r_se[1024], r_ss[1024];
    __shared__ __align__(8) unsigned long long s_mbar;

    const int t = threadIdx.x;
    const unsigned int sb  = (unsigned int)__cvta_generic_to_shared(s_tab);
    const unsigned int mbr = (unsigned int)__cvta_generic_to_shared(&s_mbar);

    const unsigned int totr  = ((unsigned int)n_leaves * 2u + 127u) & ~127u;
    const unsigned int chunk = totr / 8u;

    if (t == 0) { mbar_init(mbr, 1); mbar_expect_tx(mbr, totr); }
    __syncthreads();
    if (t < 8)
        bulk_g2s(sb + t * chunk, reinterpret_cast<const char*>(g_dleaf) + t * chunk,
                 chunk, mbr);

    const float M = 40.0f * __int_as_float(g_maxint);

    mbar_wait(mbr, 0);

    float se = 0.0f, ss = 0.0f;

    const int n4 = n_pairs >> 2;
    const int4*   l4 = reinterpret_cast<const int4*>(l_idx);
    const int4*   r4 = reinterpret_cast<const int4*>(r_idx);
    const float4* s4 = reinterpret_cast<const float4*>(sims);
    const int stride = gridDim.x * blockDim.x;

    #pragma unroll 2
    for (int i = blockIdx.x * blockDim.x + t; i < n4; i += stride) {
        int4   li = l4[i];
        int4   ri = r4[i];
        float4 si = s4[i];
        float e0 = __expf(fmaf(20.0f, __half2float(s_tab[li.x]) + __half2float(s_tab[ri.x]), -M));
        float e1 = __expf(fmaf(20.0f, __half2float(s_tab[li.y]) + __half2float(s_tab[ri.y]), -M));
        float e2 = __expf(fmaf(20.0f, __half2float(s_tab[li.z]) + __half2float(s_tab[ri.z]), -M));
        float e3 = __expf(fmaf(20.0f, __half2float(s_tab[li.w]) + __half2float(s_tab[ri.w]), -M));
        se += (e0 + e1) + (e2 + e3);
        ss  = fmaf(si.x, e0, fmaf(si.y, e1, fmaf(si.z, e2, fmaf(si.w, e3, ss))));
    }
    if (blockIdx.x == 0) {
        for (int i = n4 * 4 + t; i < n_pairs; i += blockDim.x) {
            float e = __expf(fmaf(20.0f,
                        __half2float(s_tab[l_idx[i]]) + __half2float(s_tab[r_idx[i]]), -M));
            se += e; ss = fmaf(sims[i], e, ss);
        }
    }

    r_se[t] = se; r_ss[t] = ss;
    __syncthreads();
    for (int off = 512; off > 0; off >>= 1) {
        if (t < off) {
            r_se[t] += r_se[t + off];
            r_ss[t] += r_ss[t + off];
        }
        __syncthreads();
    }
    if (t == 0) g_part[blockIdx.x] = make_float4(r_se[0], r_ss[0], 0.0f, 0.0f);
}

// ---------------- Kernel C: finalize ----------------
__global__ void finalize_kernel(float* __restrict__ out, int nb)
{
    __shared__ float r_se[256], r_ss[256], r_su[256];
    const int t = threadIdx.x;
    float se = 0.0f, ss = 0.0f, su = 0.0f;
    for (int i = t; i < nb; i += 256) {
        float4 p = g_part[i];
        se += p.x; ss += p.y;
    }
    for (int i = t; i < NSIMS; i += 256) su += g_su[i];
    r_se[t] = se; r_ss[t] = ss; r_su[t] = su;
    __syncthreads();
    for (int off = 128; off > 0; off >>= 1) {
        if (t < off) {
            r_se[t] += r_se[t + off];
            r_ss[t] += r_ss[t + off];
            r_su[t] += r_su[t + off];
        }
        __syncthreads();
    }
    if (t == 0) out[0] = r_su[0] - r_ss[0] / r_se[0];
}

// ---------------- launch ----------------
extern "C" void kernel_launch(void* const* d_in, const int* in_sizes, int n_in,
                              void* d_out, int out_size)
{
    const int*   lca    = (const int*)  d_in[0];
    const int*   l_idx  = (const int*)  d_in[1];
    const int*   r_idx  = (const int*)  d_in[2];
    const float* sims   = (const float*)d_in[3];
    const float* emb    = (const float*)d_in[4];
    const float* leaves = (const float*)d_in[5];
    const float* scale  = (const float*)d_in[6];

    const int n_pairs  = in_sizes[1];
    const int n_leaves = in_sizes[5] / 128;

    const int smemB = (n_leaves * 2 + 127) & ~127;
    cudaFuncSetAttribute(pair_reduce_kernel,
                         cudaFuncAttributeMaxDynamicSharedMemorySize,
                         (N_LEAVES_MAX * 2 + 127) & ~127);

    int sm_count = 0;
    cudaDeviceGetAttribute(&sm_count, cudaDevAttrMultiProcessorCount, 0);
    if (sm_count <= 0 || sm_count > MAXB) sm_count = 152;

    // exactly one wave: NSIMS sims-blocks + (4*SMs - NSIMS) leaf-blocks
    const int grid_a = sm_count * 4;
    leaf_dist_kernel<<<grid_a, 256>>>(lca, emb, leaves, scale,
                                      l_idx, r_idx, sims, n_leaves, n_pairs);
    pair_reduce_kernel<<<GRID_B, 1024, smemB>>>(l_idx, r_idx, sims, n_pairs, n_leaves);
    finalize_kernel<<<1, 256>>>((float*)d_out, GRID_B);
}

// round 14
// speedup vs baseline: 1.0917x; 1.0917x over previous
#include <cuda_runtime.h>
#include <cuda_fp16.h>
#include <cstdint>
#include <math.h>

// ---------------- scratch (no allocations allowed) ----------------
#define N_LEAVES_MAX 100000
#define MAXB 256
#define GRID_B 148

__device__ __align__(16) __half g_dleaf[N_LEAVES_MAX + 128];
__device__ int          g_maxint;     // max d as ordered int (positive floats)
__device__ float4       g_part[MAXB]; // (sum_exp, sum_sims_exp, sum_sims, -)
__device__ unsigned int g_ticket;     // completion ticket for fused finalize

// ---------------- mbarrier / bulk-copy helpers ----------------
__device__ __forceinline__ void mbar_init(unsigned int mbar, unsigned int cnt) {
    asm volatile("mbarrier.init.shared.b64 [%0], %1;" :: "r"(mbar), "r"(cnt) : "memory");
}
__device__ __forceinline__ void mbar_expect_tx(unsigned int mbar, unsigned int bytes) {
    asm volatile("mbarrier.arrive.expect_tx.shared.b64 _, [%0], %1;"
                 :: "r"(mbar), "r"(bytes) : "memory");
}
__device__ __forceinline__ void mbar_wait(unsigned int mbar, unsigned int phase) {
    asm volatile(
        "{\n\t"
        ".reg .pred P1;\n\t"
        "WAIT_LOOP_%=:\n\t"
        "mbarrier.try_wait.parity.acquire.cta.shared::cta.b64 P1, [%0], %1, 0x989680;\n\t"
        "@P1 bra.uni WAIT_DONE_%=;\n\t"
        "bra.uni WAIT_LOOP_%=;\n\t"
        "WAIT_DONE_%=:\n\t"
        "}"
        :: "r"(mbar), "r"(phase) : "memory");
}
__device__ __forceinline__ void bulk_g2s(unsigned int dst, const void* src,
                                         unsigned int bytes, unsigned int mbar) {
    asm volatile(
        "cp.async.bulk.shared::cluster.global.mbarrier::complete_tx::bytes [%0], [%1], %2, [%3];"
        :: "r"(dst), "l"(src), "r"(bytes), "r"(mbar) : "memory");
}

// ---------------- Kernel A: direct-LDG streaming, 8 leaves / warp-iter (R10) ----------------
__global__ __launch_bounds__(256, 4) void leaf_dist_kernel(
        const int* __restrict__ lca,
        const float* __restrict__ emb,
        const float* __restrict__ leaves,
        const float* __restrict__ scale,
        int n_leaves)
{
    __shared__ __align__(16) float s_e[128];
    __shared__ float s_red[256];
    __shared__ float s_nx, s_inv;

    const int t = threadIdx.x;

    // ---- build e1 = emb[lca]/max(||.||,1e-12) * clip(scale) ----
    const float* erow = emb + (long long)lca[0] * 128;
    float w = 0.0f;
    if (t < 128) { w = erow[t]; s_red[t] = w * w; }
    __syncthreads();
    for (int off = 64; off > 0; off >>= 1) {
        if (t < off) s_red[t] += s_red[t + off];
        __syncthreads();
    }
    if (t == 0) {
        float norm2  = s_red[0];
        float s      = fminf(fmaxf(scale[0], 0.01f), 1.0f - 0.001f);
        float factor = s / fmaxf(sqrtf(norm2), 1e-12f);
        float nx     = factor * factor * norm2;
        s_nx  = nx;
        s_inv = 1.0f / (1.0f - nx);
        s_red[0] = factor;
    }
    __syncthreads();
    if (t < 128) s_e[t] = w * s_red[0];
    __syncthreads();

    const int lane = t & 31;
    const int sub  = lane & 7;
    const int grp  = lane >> 3;
    const float4* er = reinterpret_cast<const float4*>(s_e);
    const float4 ea = er[sub], eb = er[sub + 8], ec = er[sub + 16], ed = er[sub + 24];
    const float nx = s_nx, inv = s_inv;

    const float4* leaves4 = reinterpret_cast<const float4*>(leaves);
    const int gwarp   = (blockIdx.x * blockDim.x + t) >> 5;
    const int nwarps  = (gridDim.x * blockDim.x) >> 5;
    const int ngrp8   = (n_leaves + 7) >> 3;

    float dmax = 0.0f;

    for (int g8 = gwarp; g8 < ngrp8; g8 += nwarps) {
        const int  leafA = g8 * 8 + grp;
        const int  leafB = leafA + 4;
        const bool okA   = leafA < n_leaves;
        const bool okB   = leafB < n_leaves;
        const float4* rowA = leaves4 + (size_t)(okA ? leafA : 0) * 32;
        const float4* rowB = leaves4 + (size_t)(okB ? leafB : 0) * 32;

        float4 a0 = __ldg(rowA + sub);
        float4 a1 = __ldg(rowA + sub + 8);
        float4 a2 = __ldg(rowA + sub + 16);
        float4 a3 = __ldg(rowA + sub + 24);
        float4 b0 = __ldg(rowB + sub);
        float4 b1 = __ldg(rowB + sub + 8);
        float4 b2 = __ldg(rowB + sub + 16);
        float4 b3 = __ldg(rowB + sub + 24);

        float dotA, nyA;
        dotA = ea.x * a0.x + ea.y * a0.y + ea.z * a0.z + ea.w * a0.w;
        nyA  = a0.x * a0.x + a0.y * a0.y + a0.z * a0.z + a0.w * a0.w;
        dotA = fmaf(eb.x, a1.x, fmaf(eb.y, a1.y, fmaf(eb.z, a1.z, fmaf(eb.w, a1.w, dotA))));
        nyA  = fmaf(a1.x, a1.x, fmaf(a1.y, a1.y, fmaf(a1.z, a1.z, fmaf(a1.w, a1.w, nyA))));
        dotA = fmaf(ec.x, a2.x, fmaf(ec.y, a2.y, fmaf(ec.z, a2.z, fmaf(ec.w, a2.w, dotA))));
        nyA  = fmaf(a2.x, a2.x, fmaf(a2.y, a2.y, fmaf(a2.z, a2.z, fmaf(a2.w, a2.w, nyA))));
        dotA = fmaf(ed.x, a3.x, fmaf(ed.y, a3.y, fmaf(ed.z, a3.z, fmaf(ed.w, a3.w, dotA))));
        nyA  = fmaf(a3.x, a3.x, fmaf(a3.y, a3.y, fmaf(a3.z, a3.z, fmaf(a3.w, a3.w, nyA))));

        float dotB, nyB;
        dotB = ea.x * b0.x + ea.y * b0.y + ea.z * b0.z + ea.w * b0.w;
        nyB  = b0.x * b0.x + b0.y * b0.y + b0.z * b0.z + b0.w * b0.w;
        dotB = fmaf(eb.x, b1.x, fmaf(eb.y, b1.y, fmaf(eb.z, b1.z, fmaf(eb.w, b1.w, dotB))));
        nyB  = fmaf(b1.x, b1.x, fmaf(b1.y, b1.y, fmaf(b1.z, b1.z, fmaf(b1.w, b1.w, nyB))));
        dotB = fmaf(ec.x, b2.x, fmaf(ec.y, b2.y, fmaf(ec.z, b2.z, fmaf(ec.w, b2.w, dotB))));
        nyB  = fmaf(b2.x, b2.x, fmaf(b2.y, b2.y, fmaf(b2.z, b2.z, fmaf(b2.w, b2.w, nyB))));
        dotB = fmaf(ed.x, b3.x, fmaf(ed.y, b3.y, fmaf(ed.z, b3.z, fmaf(ed.w, b3.w, dotB))));
        nyB  = fmaf(b3.x, b3.x, fmaf(b3.y, b3.y, fmaf(b3.z, b3.z, fmaf(b3.w, b3.w, nyB))));

        #pragma unroll
        for (int o = 1; o < 8; o <<= 1) {
            dotA += __shfl_xor_sync(0xffffffffu, dotA, o);
            nyA  += __shfl_xor_sync(0xffffffffu, nyA,  o);
            dotB += __shfl_xor_sync(0xffffffffu, dotB, o);
            nyB  += __shfl_xor_sync(0xffffffffu, nyB,  o);
        }

        if (sub == 0) {
            if (okA) {
                float sq  = nx - 2.0f * dotA + nyA;
                float arg = fmaxf(1.0f + 2.0f * sq * inv / (1.0f - nyA), 1.0f + 1e-7f);
                float d = acoshf(arg);
                g_dleaf[leafA] = __float2half(d);
                dmax = fmaxf(dmax, d);
            }
            if (okB) {
                float sq  = nx - 2.0f * dotB + nyB;
                float arg = fmaxf(1.0f + 2.0f * sq * inv / (1.0f - nyB), 1.0f + 1e-7f);
                float d = acoshf(arg);
                g_dleaf[leafB] = __float2half(d);
                dmax = fmaxf(dmax, d);
            }
        }
    }

    // ---- block max -> global atomicMax (deterministic) ----
    s_red[t] = dmax;
    __syncthreads();
    for (int off = 128; off > 0; off >>= 1) {
        if (t < off) s_red[t] = fmaxf(s_red[t], s_red[t + off]);
        __syncthreads();
    }
    if (t == 0) atomicMax(&g_maxint, __float_as_int(s_red[0]));
}

// ---------------- Kernel B: softmax partials + fused finalize ----------------
// Pair data preloaded BEFORE the staging wait (each thread owns <=2 quads at
// GRID_B*1024 threads vs n_pairs/4 quads) -> pair DRAM stream overlaps the
// 200KB/SM table staging. Last block (ticket) reduces partials and writes out.
__global__ __launch_bounds__(1024) void pair_reduce_kernel(
        const int* __restrict__ l_idx,
        const int* __restrict__ r_idx,
        const float* __restrict__ sims,
        float* __restrict__ out,
        int n_pairs, int n_leaves)
{
    extern __shared__ __half s_tab[];
    __shared__ float r_se[1024], r_ss[1024], r_su[1024];
    __shared__ __align__(8) unsigned long long s_mbar;
    __shared__ int s_last;

    const int t = threadIdx.x;
    const unsigned int sb  = (unsigned int)__cvta_generic_to_shared(s_tab);
    const unsigned int mbr = (unsigned int)__cvta_generic_to_shared(&s_mbar);

    const unsigned int totr  = ((unsigned int)n_leaves * 2u + 127u) & ~127u;
    const unsigned int chunk = totr / 8u;

    if (t == 0) { mbar_init(mbr, 1); mbar_expect_tx(mbr, totr); }
    __syncthreads();
    if (t < 8)
        bulk_g2s(sb + t * chunk, reinterpret_cast<const char*>(g_dleaf) + t * chunk,
                 chunk, mbr);

    const float M = 40.0f * __int_as_float(g_maxint);

    // ---- preload pair quads BEFORE waiting on the table ----
    const int n4 = n_pairs >> 2;
    const int4*   l4 = reinterpret_cast<const int4*>(l_idx);
    const int4*   r4 = reinterpret_cast<const int4*>(r_idx);
    const float4* s4 = reinterpret_cast<const float4*>(sims);
    const int stride = gridDim.x * blockDim.x;

    const int  i0 = blockIdx.x * blockDim.x + t;
    const int  i1 = i0 + stride;
    const bool v0 = i0 < n4;
    const bool v1 = i1 < n4;

    int4 li0 = {0,0,0,0}, ri0 = {0,0,0,0}, li1 = {0,0,0,0}, ri1 = {0,0,0,0};
    float4 si0 = {0,0,0,0}, si1 = {0,0,0,0};
    if (v0) { li0 = l4[i0]; ri0 = r4[i0]; si0 = s4[i0]; }
    if (v1) { li1 = l4[i1]; ri1 = r4[i1]; si1 = s4[i1]; }

    mbar_wait(mbr, 0);     // table staged; pair loads already in flight/done

    float se = 0.0f, ss = 0.0f, su = 0.0f;

    if (v0) {
        float e0 = __expf(fmaf(20.0f, __half2float(s_tab[li0.x]) + __half2float(s_tab[ri0.x]), -M));
        float e1 = __expf(fmaf(20.0f, __half2float(s_tab[li0.y]) + __half2float(s_tab[ri0.y]), -M));
        float e2 = __expf(fmaf(20.0f, __half2float(s_tab[li0.z]) + __half2float(s_tab[ri0.z]), -M));
        float e3 = __expf(fmaf(20.0f, __half2float(s_tab[li0.w]) + __half2float(s_tab[ri0.w]), -M));
        se += (e0 + e1) + (e2 + e3);
        ss  = fmaf(si0.x, e0, fmaf(si0.y, e1, fmaf(si0.z, e2, fmaf(si0.w, e3, ss))));
        su += (si0.x + si0.y) + (si0.z + si0.w);
    }
    if (v1) {
        float e0 = __expf(fmaf(20.0f, __half2float(s_tab[li1.x]) + __half2float(s_tab[ri1.x]), -M));
        float e1 = __expf(fmaf(20.0f, __half2float(s_tab[li1.y]) + __half2float(s_tab[ri1.y]), -M));
        float e2 = __expf(fmaf(20.0f, __half2float(s_tab[li1.z]) + __half2float(s_tab[ri1.z]), -M));
        float e3 = __expf(fmaf(20.0f, __half2float(s_tab[li1.w]) + __half2float(s_tab[ri1.w]), -M));
        se += (e0 + e1) + (e2 + e3);
        ss  = fmaf(si1.x, e0, fmaf(si1.y, e1, fmaf(si1.z, e2, fmaf(si1.w, e3, ss))));
        su += (si1.x + si1.y) + (si1.z + si1.w);
    }
    // generic continuation (covers n4 > 2*stride) + scalar tail
    for (int i = i1 + stride; i < n4; i += stride) {
        int4   li = l4[i];
        int4   ri = r4[i];
        float4 si = s4[i];
        float e0 = __expf(fmaf(20.0f, __half2float(s_tab[li.x]) + __half2float(s_tab[ri.x]), -M));
        float e1 = __expf(fmaf(20.0f, __half2float(s_tab[li.y]) + __half2float(s_tab[ri.y]), -M));
        float e2 = __expf(fmaf(20.0f, __half2float(s_tab[li.z]) + __half2float(s_tab[ri.z]), -M));
        float e3 = __expf(fmaf(20.0f, __half2float(s_tab[li.w]) + __half2float(s_tab[ri.w]), -M));
        se += (e0 + e1) + (e2 + e3);
        ss  = fmaf(si.x, e0, fmaf(si.y, e1, fmaf(si.z, e2, fmaf(si.w, e3, ss))));
        su += (si.x + si.y) + (si.z + si.w);
    }
    if (blockIdx.x == 0) {
        for (int i = n4 * 4 + t; i < n_pairs; i += blockDim.x) {
            float e = __expf(fmaf(20.0f,
                        __half2float(s_tab[l_idx[i]]) + __half2float(s_tab[r_idx[i]]), -M));
            float si = sims[i];
            se += e; ss = fmaf(si, e, ss); su += si;
        }
    }

    // ---- block reduction ----
    r_se[t] = se; r_ss[t] = ss; r_su[t] = su;
    __syncthreads();
    for (int off = 512; off > 0; off >>= 1) {
        if (t < off) {
            r_se[t] += r_se[t + off];
            r_ss[t] += r_ss[t + off];
            r_su[t] += r_su[t + off];
        }
        __syncthreads();
    }

    // ---- fused finalize: last block reduces all partials ----
    if (t == 0) {
        g_part[blockIdx.x] = make_float4(r_se[0], r_ss[0], r_su[0], 0.0f);
        __threadfence();
        unsigned int rank = atomicAdd(&g_ticket, 1u);
        s_last = (rank == gridDim.x - 1) ? 1 : 0;
    }
    __syncthreads();

    if (s_last) {
        __threadfence();
        float fse = 0.0f, fss = 0.0f, fsu = 0.0f;
        if (t < gridDim.x) {
            const float4* gp = (const float4*)&g_part[t];
            float4 p;
            p.x = __ldcg(&gp->x); p.y = __ldcg(&gp->y); p.z = __ldcg(&gp->z);
            fse = p.x; fss = p.y; fsu = p.z;
        }
        r_se[t] = fse; r_ss[t] = fss; r_su[t] = fsu;
        __syncthreads();
        for (int off = 512; off > 0; off >>= 1) {
            if (t < off) {
                r_se[t] += r_se[t + off];
                r_ss[t] += r_ss[t + off];
                r_su[t] += r_su[t + off];
            }
            __syncthreads();
        }
        if (t == 0) {
            out[0] = r_su[0] - r_ss[0] / r_se[0];   // sum(sims) - w_ord
            g_ticket = 0;                           // reset for next graph replay
        }
    }
}

// ---------------- launch ----------------
extern "C" void kernel_launch(void* const* d_in, const int* in_sizes, int n_in,
                              void* d_out, int out_size)
{
    const int*   lca    = (const int*)  d_in[0];
    const int*   l_idx  = (const int*)  d_in[1];
    const int*   r_idx  = (const int*)  d_in[2];
    const float* sims   = (const float*)d_in[3];
    const float* emb    = (const float*)d_in[4];
    const float* leaves = (const float*)d_in[5];
    const float* scale  = (const float*)d_in[6];

    const int n_pairs  = in_sizes[1];
    const int n_leaves = in_sizes[5] / 128;

    const int smemB = (n_leaves * 2 + 127) & ~127;
    cudaFuncSetAttribute(pair_reduce_kernel,
                         cudaFuncAttributeMaxDynamicSharedMemorySize,
                         (N_LEAVES_MAX * 2 + 127) & ~127);

    int sm_count = 0;
    cudaDeviceGetAttribute(&sm_count, cudaDevAttrMultiProcessorCount, 0);
    if (sm_count <= 0 || sm_count > MAXB) sm_count = 148;

    leaf_dist_kernel<<<sm_count * 4, 256>>>(lca, emb, leaves, scale, n_leaves);
    pair_reduce_kernel<<<GRID_B, 1024, smemB>>>(l_idx, r_idx, sims,
                                                (float*)d_out, n_pairs, n_leaves);
}